// round 11
// baseline (speedup 1.0000x reference)
#include <cuda_runtime.h>
#include <cuda_bf16.h>

#define SEQ_LEN 512
#define BATCH   256
#define CAUSES  64
#define STATES  512
#define OUT_DIM 256
#define RPC     8
#define NCTA    (BATCH / RPC)      // 32
#define NT      512
#define HALFT   256

#define ALPHA_X 0.1f
#define ALPHA_H 0.1f

typedef unsigned long long u64;

// ---------------- packed weight scratch (device globals: allocation-free) ----
__device__ float g_wrP[STATES/2 * STATES * 2];            // 262144
__device__ float g_wcB[CAUSES/2 * STATES * 2];            // 32768
__device__ float g_woC[STATES/4 * OUT_DIM * 4];           // 131072
__device__ float g_woD[OUT_DIM/2 * STATES * 2];           // 131072
__device__ float g_wcE[STATES/2 * CAUSES * 2];            // 32768

// ---------------- packed f32x2 helpers (PTX; ptxas won't auto-fuse) ----
__device__ __forceinline__ u64 dup2(float s) {
    u64 r; asm("mov.b64 %0, {%1, %1};" : "=l"(r) : "f"(s)); return r;
}
__device__ __forceinline__ u64 pack2(float a, float b) {
    u64 r; asm("mov.b64 %0, {%1, %2};" : "=l"(r) : "f"(a), "f"(b)); return r;
}
__device__ __forceinline__ void fma2(u64& d, u64 a, u64 b) {
    asm("fma.rn.f32x2 %0, %1, %2, %3;" : "=l"(d) : "l"(a), "l"(b), "l"(d));
}
__device__ __forceinline__ void add2(u64& d, u64 a, u64 b) {
    asm("add.rn.f32x2 %0, %1, %2;" : "=l"(d) : "l"(a), "l"(b));
}
__device__ __forceinline__ void unpack2(u64 v, float& lo, float& hi) {
    asm("mov.b64 {%0, %1}, %2;" : "=f"(lo), "=f"(hi) : "l"(v));
}

// ---------------- single merged prologue pack kernel ----------
__global__ void pack_all(const float* __restrict__ w_r,
                         const float* __restrict__ w_c,
                         const float* __restrict__ w_o) {
    int idx = blockIdx.x * 256 + threadIdx.x;
    if (idx < 262144) {                                        // wrP
        int k2 = idx >> 10, rem = idx & 1023;
        int jp = rem >> 2, c = rem & 3;
        int j = jp * 2 + (c & 1), k = k2 * 2 + (c >> 1);
        g_wrP[idx] = w_r[j * STATES + k];
        return;
    }
    idx -= 262144;
    if (idx < 32768) {                                         // wcB
        int m2 = idx >> 10, rem = idx & 1023;
        int jp = rem >> 2, c = rem & 3;
        int j = jp * 2 + (c & 1), m = m2 * 2 + (c >> 1);
        g_wcB[idx] = w_c[j * CAUSES + m];
        return;
    }
    idx -= 32768;
    if (idx < 131072) {                                        // woC
        int j4 = idx >> 10, rem = idx & 1023;
        int o = rem >> 2, jj = rem & 3;
        g_woC[idx] = w_o[o * STATES + j4 * 4 + jj];
        return;
    }
    idx -= 131072;
    if (idx < 131072) {                                        // woD
        int o2 = idx >> 10, rem = idx & 1023;
        int jp = rem >> 2, c = rem & 3;
        int j = jp * 2 + (c & 1), o = o2 * 2 + (c >> 1);
        g_woD[idx] = w_o[o * STATES + j];
        return;
    }
    idx -= 131072;
    {                                                          // wcE (32768)
        int j2 = idx >> 7, rem = idx & 127;
        int m = rem >> 1, jj = rem & 1;
        g_wcE[idx] = w_c[(j2 * 2 + jj) * CAUSES + m];
    }
}

// ---- dynamic smem layout (u64 units) ----
#define OFF_TH    0                   // [512 k][8 r]  tanh(h_post) dup'd    4096
#define OFF_TP    4096                // [512 j][4 rp] tanh(h_prior) pairs   2048
#define OFF_ERR   6144                // [256 o][8 r]  error dup'd           2048
#define OFF_EH    8192                // [256 j2][8 r] error_h j-pairs       2048
#define OFF_C     10240               // [64 m][8 r]   c dup'd                512
#define OFF_PART  10752               // [256][8]      partials              2048
#define SMEM_U64  12800
#define SMEM_BYTES (SMEM_U64 * 8)     // 102400

// ---------------- main persistent recurrence kernel (RPC=8, 2-way split) ----
__global__ __launch_bounds__(NT, 1)
void pc_rnn_kernel(const float* __restrict__ x,
                   const float* __restrict__ c_init,
                   const float* __restrict__ h_init,
                   const float* __restrict__ b_o,
                   const float* __restrict__ b_r,
                   float* __restrict__ out)
{
    extern __shared__ __align__(16) u64 S[];
    u64* s_th2  = S + OFF_TH;
    u64* s_tp2  = S + OFF_TP;
    u64* s_err2 = S + OFF_ERR;
    u64* s_eh2  = S + OFF_EH;
    u64* s_c2   = S + OFF_C;
    u64* s_part = S + OFF_PART;

    const int tid  = threadIdx.x;
    const int lid  = tid & (HALFT - 1);
    const int uppr = tid >> 8;                // 0 = finalizer half
    const int b0   = blockIdx.x * RPC;
    const int j0   = lid * 2;

    const float4* __restrict__ wrB = (const float4*)g_wrP;
    const float4* __restrict__ wcB = (const float4*)g_wcB;
    const float4* __restrict__ woC = (const float4*)g_woC;
    const float4* __restrict__ woD = (const float4*)g_woD;
    const u64*    __restrict__ wcE = (const u64*)g_wcE;

    float h0[RPC], h1[RPC], hp0[RPC], hp1[RPC], tp0[RPC], tp1[RPC];
    float rb0 = 0.f, rb1 = 0.f, rbo = 0.f;
    float creg_a = 0.f, creg_b = 0.f;
    const int cm = lid & 63, crp = lid >> 6;   // (m, row-pair) for phase E

    if (!uppr) {
#pragma unroll
        for (int r = 0; r < RPC; ++r) {
            h0[r] = h_init[(size_t)(b0 + r) * STATES + j0];
            h1[r] = h_init[(size_t)(b0 + r) * STATES + j0 + 1];
            s_th2[(j0)     * RPC + r] = dup2(tanhf(h0[r]));
            s_th2[(j0 + 1) * RPC + r] = dup2(tanhf(h1[r]));
        }
        rb0 = b_r[j0]; rb1 = b_r[j0 + 1];
        rbo = b_o[lid];
        creg_a = c_init[(size_t)(b0 + 2 * crp)     * CAUSES + cm];
        creg_b = c_init[(size_t)(b0 + 2 * crp + 1) * CAUSES + cm];
        s_c2[cm * RPC + 2 * crp]     = dup2(creg_a);
        s_c2[cm * RPC + 2 * crp + 1] = dup2(creg_b);
    }
    __syncthreads();

    for (int t = 0; t < SEQ_LEN; ++t) {
        // prefetch x_t (finalizer half; hidden behind phase B)
        float xr[RPC];
        if (!uppr) {
#pragma unroll
            for (int r = 0; r < RPC; ++r)
                xr[r] = x[((size_t)t * BATCH + b0 + r) * OUT_DIM + lid];
        }

        // ---------- Phase B partial: th@WrT + c@WcT over this half's k range ----------
        u64 acc[RPC];
#pragma unroll
        for (int r = 0; r < RPC; ++r) acc[r] = 0ULL;
        {
            const int bk2 = uppr * 128;
#pragma unroll 4
            for (int k2i = 0; k2i < 128; ++k2i) {
                const int k2 = bk2 + k2i;
                float4 w = wrB[k2 * 256 + lid];
                u64 wlo = pack2(w.x, w.y), whi = pack2(w.z, w.w);
                const u64* th = &s_th2[(k2 * 2) * RPC];   // 16 u64: k row-set, k+1 row-set
                ulonglong2 t0 = *(const ulonglong2*)(th);
                ulonglong2 t1 = *(const ulonglong2*)(th + 2);
                ulonglong2 t2 = *(const ulonglong2*)(th + 4);
                ulonglong2 t3 = *(const ulonglong2*)(th + 6);
                ulonglong2 t4 = *(const ulonglong2*)(th + 8);
                ulonglong2 t5 = *(const ulonglong2*)(th + 10);
                ulonglong2 t6 = *(const ulonglong2*)(th + 12);
                ulonglong2 t7 = *(const ulonglong2*)(th + 14);
                fma2(acc[0], t0.x, wlo); fma2(acc[1], t0.y, wlo);
                fma2(acc[2], t1.x, wlo); fma2(acc[3], t1.y, wlo);
                fma2(acc[4], t2.x, wlo); fma2(acc[5], t2.y, wlo);
                fma2(acc[6], t3.x, wlo); fma2(acc[7], t3.y, wlo);
                fma2(acc[0], t4.x, whi); fma2(acc[1], t4.y, whi);
                fma2(acc[2], t5.x, whi); fma2(acc[3], t5.y, whi);
                fma2(acc[4], t6.x, whi); fma2(acc[5], t6.y, whi);
                fma2(acc[6], t7.x, whi); fma2(acc[7], t7.y, whi);
            }
            const int bm2 = uppr * 16;
#pragma unroll 4
            for (int m2i = 0; m2i < 16; ++m2i) {
                const int m2 = bm2 + m2i;
                float4 w = wcB[m2 * 256 + lid];
                u64 wlo = pack2(w.x, w.y), whi = pack2(w.z, w.w);
                const u64* cb = &s_c2[(m2 * 2) * RPC];
                ulonglong2 t0 = *(const ulonglong2*)(cb);
                ulonglong2 t1 = *(const ulonglong2*)(cb + 2);
                ulonglong2 t2 = *(const ulonglong2*)(cb + 4);
                ulonglong2 t3 = *(const ulonglong2*)(cb + 6);
                ulonglong2 t4 = *(const ulonglong2*)(cb + 8);
                ulonglong2 t5 = *(const ulonglong2*)(cb + 10);
                ulonglong2 t6 = *(const ulonglong2*)(cb + 12);
                ulonglong2 t7 = *(const ulonglong2*)(cb + 14);
                fma2(acc[0], t0.x, wlo); fma2(acc[1], t0.y, wlo);
                fma2(acc[2], t1.x, wlo); fma2(acc[3], t1.y, wlo);
                fma2(acc[4], t2.x, wlo); fma2(acc[5], t2.y, wlo);
                fma2(acc[6], t3.x, wlo); fma2(acc[7], t3.y, wlo);
                fma2(acc[0], t4.x, whi); fma2(acc[1], t4.y, whi);
                fma2(acc[2], t5.x, whi); fma2(acc[3], t5.y, whi);
                fma2(acc[4], t6.x, whi); fma2(acc[5], t6.y, whi);
                fma2(acc[6], t7.x, whi); fma2(acc[7], t7.y, whi);
            }
        }
        if (uppr) {
#pragma unroll
            for (int r = 0; r < RPC; ++r) s_part[lid * 8 + r] = acc[r];
        }
        __syncthreads();

        // ---------- Phase B finalize: h_prior, tanh(h_prior) ----------
        if (!uppr) {
#pragma unroll
            for (int r = 0; r < RPC; ++r) {
                add2(acc[r], acc[r], s_part[lid * 8 + r]);
                float a0, a1; unpack2(acc[r], a0, a1);
                hp0[r] = 0.9f * h0[r] + 0.1f * (a0 + rb0);
                hp1[r] = 0.9f * h1[r] + 0.1f * (a1 + rb1);
                tp0[r] = tanhf(hp0[r]);
                tp1[r] = tanhf(hp1[r]);
            }
            ulonglong2 v0, v1;
            v0.x = pack2(tp0[0], tp0[1]); v0.y = pack2(tp0[2], tp0[3]);
            v1.x = pack2(tp0[4], tp0[5]); v1.y = pack2(tp0[6], tp0[7]);
            *(ulonglong2*)&s_tp2[j0 * 4]     = v0;
            *(ulonglong2*)&s_tp2[j0 * 4 + 2] = v1;
            v0.x = pack2(tp1[0], tp1[1]); v0.y = pack2(tp1[2], tp1[3]);
            v1.x = pack2(tp1[4], tp1[5]); v1.y = pack2(tp1[6], tp1[7]);
            *(ulonglong2*)&s_tp2[(j0 + 1) * 4]     = v0;
            *(ulonglong2*)&s_tp2[(j0 + 1) * 4 + 2] = v1;
        }
        __syncthreads();

        // ---------- Phase C partial: tp@WoT over this half's j range (o = lid) ----------
        {
            u64 e[4];
#pragma unroll
            for (int p = 0; p < 4; ++p) e[p] = 0ULL;
            const int bj4 = uppr * 64;
#pragma unroll 4
            for (int j4i = 0; j4i < 64; ++j4i) {
                const int j4 = bj4 + j4i;
                float4 w = woC[j4 * 256 + lid];
                u64 w0 = dup2(w.x), w1 = dup2(w.y), w2 = dup2(w.z), w3 = dup2(w.w);
                const u64* tp = &s_tp2[j4 * 16];          // 4 j's × 4 row-pairs
                ulonglong2 p0 = *(const ulonglong2*)(tp);
                ulonglong2 p1 = *(const ulonglong2*)(tp + 2);
                ulonglong2 p2 = *(const ulonglong2*)(tp + 4);
                ulonglong2 p3 = *(const ulonglong2*)(tp + 6);
                ulonglong2 p4 = *(const ulonglong2*)(tp + 8);
                ulonglong2 p5 = *(const ulonglong2*)(tp + 10);
                ulonglong2 p6 = *(const ulonglong2*)(tp + 12);
                ulonglong2 p7 = *(const ulonglong2*)(tp + 14);
                fma2(e[0], p0.x, w0); fma2(e[1], p0.y, w0);
                fma2(e[2], p1.x, w0); fma2(e[3], p1.y, w0);
                fma2(e[0], p2.x, w1); fma2(e[1], p2.y, w1);
                fma2(e[2], p3.x, w1); fma2(e[3], p3.y, w1);
                fma2(e[0], p4.x, w2); fma2(e[1], p4.y, w2);
                fma2(e[2], p5.x, w2); fma2(e[3], p5.y, w2);
                fma2(e[0], p6.x, w3); fma2(e[1], p6.y, w3);
                fma2(e[2], p7.x, w3); fma2(e[3], p7.y, w3);
            }
            if (uppr) {
#pragma unroll
                for (int p = 0; p < 4; ++p) s_part[lid * 8 + p] = e[p];
            } else {
#pragma unroll
                for (int p = 0; p < 4; ++p) acc[p] = e[p];
            }
        }
        __syncthreads();

        // ---------- Phase C finalize: err = pred - x_t; out + s_err2 ----------
        if (!uppr) {
            float er[RPC];
#pragma unroll
            for (int p = 0; p < 4; ++p) {
                add2(acc[p], acc[p], s_part[lid * 8 + p]);
                float qa, qb; unpack2(acc[p], qa, qb);
                er[2 * p]     = (qa + rbo) - xr[2 * p];
                er[2 * p + 1] = (qb + rbo) - xr[2 * p + 1];
            }
            size_t ob = ((size_t)t * BATCH + b0) * OUT_DIM + lid;
#pragma unroll
            for (int r = 0; r < RPC; ++r) {
                out[ob + (size_t)r * OUT_DIM] = er[r];
                s_err2[lid * RPC + r] = dup2(er[r]);
            }
        }
        __syncthreads();

        // ---------- Phase D partial: err@Wo over this half's o range ----------
        {
            u64 g[RPC];
#pragma unroll
            for (int r = 0; r < RPC; ++r) g[r] = 0ULL;
            const int bo2 = uppr * 64;
#pragma unroll 4
            for (int o2i = 0; o2i < 64; ++o2i) {
                const int o2 = bo2 + o2i;
                float4 w = woD[o2 * 256 + lid];
                u64 wlo = pack2(w.x, w.y), whi = pack2(w.z, w.w);
                const u64* eb = &s_err2[(o2 * 2) * RPC];
                ulonglong2 t0 = *(const ulonglong2*)(eb);
                ulonglong2 t1 = *(const ulonglong2*)(eb + 2);
                ulonglong2 t2 = *(const ulonglong2*)(eb + 4);
                ulonglong2 t3 = *(const ulonglong2*)(eb + 6);
                ulonglong2 t4 = *(const ulonglong2*)(eb + 8);
                ulonglong2 t5 = *(const ulonglong2*)(eb + 10);
                ulonglong2 t6 = *(const ulonglong2*)(eb + 12);
                ulonglong2 t7 = *(const ulonglong2*)(eb + 14);
                fma2(g[0], t0.x, wlo); fma2(g[1], t0.y, wlo);
                fma2(g[2], t1.x, wlo); fma2(g[3], t1.y, wlo);
                fma2(g[4], t2.x, wlo); fma2(g[5], t2.y, wlo);
                fma2(g[6], t3.x, wlo); fma2(g[7], t3.y, wlo);
                fma2(g[0], t4.x, whi); fma2(g[1], t4.y, whi);
                fma2(g[2], t5.x, whi); fma2(g[3], t5.y, whi);
                fma2(g[4], t6.x, whi); fma2(g[5], t6.y, whi);
                fma2(g[6], t7.x, whi); fma2(g[7], t7.y, whi);
            }
            if (uppr) {
#pragma unroll
                for (int r = 0; r < RPC; ++r) s_part[lid * 8 + r] = g[r];
            } else {
#pragma unroll
                for (int r = 0; r < RPC; ++r) acc[r] = g[r];
            }
        }
        __syncthreads();

        // ---------- Phase D finalize: h_post, th = tanh(h_post), eh ----------
        if (!uppr) {
#pragma unroll
            for (int r = 0; r < RPC; ++r) {
                add2(acc[r], acc[r], s_part[lid * 8 + r]);
                float g0, g1; unpack2(acc[r], g0, g1);
                float d0 = ALPHA_X * (1.0f - tp0[r] * tp0[r]) * g0;
                float d1 = ALPHA_X * (1.0f - tp1[r] * tp1[r]) * g1;
                h0[r] = hp0[r] - d0;
                h1[r] = hp1[r] - d1;
                s_eh2[lid * RPC + r] = pack2(d0, d1);
                s_th2[(j0)     * RPC + r] = dup2(tanhf(h0[r]));
                s_th2[(j0 + 1) * RPC + r] = dup2(tanhf(h1[r]));
            }
        }
        __syncthreads();

        // ---------- Phase E partial: eh@Wc over this half's j range ----------
        {
            u64 cea = 0ULL, ceb = 0ULL;
            const int bj2 = uppr * 128;
#pragma unroll 8
            for (int j2i = 0; j2i < 128; ++j2i) {
                const int j2 = bj2 + j2i;
                u64 w = wcE[j2 * 64 + cm];
                fma2(cea, s_eh2[j2 * RPC + 2 * crp],     w);
                fma2(ceb, s_eh2[j2 * RPC + 2 * crp + 1], w);
            }
            if (uppr) {
                s_part[lid * 8]     = cea;
                s_part[lid * 8 + 1] = ceb;
            } else {
                acc[0] = cea; acc[1] = ceb;
            }
        }
        __syncthreads();

        // ---------- Phase E finalize: c update ----------
        if (!uppr) {
            add2(acc[0], acc[0], s_part[lid * 8]);
            add2(acc[1], acc[1], s_part[lid * 8 + 1]);
            float la, ha, lb, hb;
            unpack2(acc[0], la, ha);
            unpack2(acc[1], lb, hb);
            creg_a = creg_a - ALPHA_H * (la + ha);
            creg_b = creg_b - ALPHA_H * (lb + hb);
            s_c2[cm * RPC + 2 * crp]     = dup2(creg_a);
            s_c2[cm * RPC + 2 * crp + 1] = dup2(creg_b);
        }
        __syncthreads();
    }
}

extern "C" void kernel_launch(void* const* d_in, const int* in_sizes, int n_in,
                              void* d_out, int out_size) {
    const float* x      = (const float*)d_in[0];
    const float* c_init = (const float*)d_in[1];
    const float* h_init = (const float*)d_in[2];
    const float* w_o    = (const float*)d_in[3];
    const float* b_o    = (const float*)d_in[4];
    const float* w_c    = (const float*)d_in[5];
    const float* w_r    = (const float*)d_in[6];
    const float* b_r    = (const float*)d_in[7];
    float* out          = (float*)d_out;

    pack_all<<<2304, 256>>>(w_r, w_c, w_o);

    cudaFuncSetAttribute(pc_rnn_kernel,
                         cudaFuncAttributeMaxDynamicSharedMemorySize, SMEM_BYTES);
    pc_rnn_kernel<<<NCTA, NT, SMEM_BYTES>>>(x, c_init, h_init, b_o, b_r, out);
}

// round 15
// speedup vs baseline: 3.1807x; 3.1807x over previous
#include <cuda_runtime.h>
#include <cuda_bf16.h>

#define SEQ_LEN 512
#define BATCH   256
#define CAUSES  64
#define STATES  512
#define OUT_DIM 256
#define RPC     4
#define NCTA    (BATCH / RPC)
#define NT      1024
#define QT      256        // threads per quarter

#define ALPHA_X 0.1f
#define ALPHA_H 0.1f

typedef unsigned long long u64;
typedef unsigned int u32;

// ---------------- packed bf16 weight scratch (device globals) ----
__device__ __align__(16) __nv_bfloat16 g_wrP[STATES/2 * STATES * 2];   // 262144 elems
__device__ __align__(16) __nv_bfloat16 g_wcB[CAUSES/2 * STATES * 2];   // 32768
__device__ __align__(16) __nv_bfloat16 g_woC[STATES/4 * OUT_DIM * 4];  // 131072
__device__ __align__(16) __nv_bfloat16 g_woD[OUT_DIM/2 * STATES * 2];  // 131072
__device__ __align__(16) __nv_bfloat16 g_wcE[STATES/2 * CAUSES * 2];   // 32768

// ---------------- packed f32x2 helpers (PTX; ptxas won't auto-fuse) ----
__device__ __forceinline__ u64 dup2(float s) {
    u64 r; asm("mov.b64 %0, {%1, %1};" : "=l"(r) : "f"(s)); return r;
}
__device__ __forceinline__ u64 pack2(float a, float b) {
    u64 r; asm("mov.b64 %0, {%1, %2};" : "=l"(r) : "f"(a), "f"(b)); return r;
}
__device__ __forceinline__ void fma2(u64& d, u64 a, u64 b) {
    asm("fma.rn.f32x2 %0, %1, %2, %3;" : "=l"(d) : "l"(a), "l"(b), "l"(d));
}
__device__ __forceinline__ void add2(u64& d, u64 a, u64 b) {
    asm("add.rn.f32x2 %0, %1, %2;" : "=l"(d) : "l"(a), "l"(b));
}
__device__ __forceinline__ void unpack2(u64 v, float& lo, float& hi) {
    asm("mov.b64 {%0, %1}, %2;" : "=f"(lo), "=f"(hi) : "l"(v));
}
// bf16x2 (u32) -> f32x2 (u64): lo elem = low 16 bits
__device__ __forceinline__ u64 bf2(u32 v) {
    u32 a, b; u64 r;
    asm("shl.b32 %0, %1, 16;" : "=r"(a) : "r"(v));
    asm("and.b32 %0, %1, 0xFFFF0000;" : "=r"(b) : "r"(v));
    asm("mov.b64 %0, {%1, %2};" : "=l"(r) : "r"(a), "r"(b));
    return r;
}
// bf16x2 (u32) -> two dup'd f32x2
__device__ __forceinline__ void bfdup(u32 v, u64& dlo, u64& dhi) {
    u32 a, b;
    asm("shl.b32 %0, %1, 16;" : "=r"(a) : "r"(v));
    asm("and.b32 %0, %1, 0xFFFF0000;" : "=r"(b) : "r"(v));
    asm("mov.b64 %0, {%1, %1};" : "=l"(dlo) : "r"(a));
    asm("mov.b64 %0, {%1, %1};" : "=l"(dhi) : "r"(b));
}

// ---------------- single merged prologue pack kernel (fp32 -> bf16) ----------
__global__ void pack_all(const float* __restrict__ w_r,
                         const float* __restrict__ w_c,
                         const float* __restrict__ w_o) {
    int idx = blockIdx.x * 256 + threadIdx.x;
    if (idx < 262144) {                                        // wrP
        int k2 = idx >> 10, rem = idx & 1023;
        int jp = rem >> 2, c = rem & 3;
        int j = jp * 2 + (c & 1), k = k2 * 2 + (c >> 1);
        g_wrP[idx] = __float2bfloat16(w_r[j * STATES + k]);
        return;
    }
    idx -= 262144;
    if (idx < 32768) {                                         // wcB
        int m2 = idx >> 10, rem = idx & 1023;
        int jp = rem >> 2, c = rem & 3;
        int j = jp * 2 + (c & 1), m = m2 * 2 + (c >> 1);
        g_wcB[idx] = __float2bfloat16(w_c[j * CAUSES + m]);
        return;
    }
    idx -= 32768;
    if (idx < 131072) {                                        // woC
        int j4 = idx >> 10, rem = idx & 1023;
        int o = rem >> 2, jj = rem & 3;
        g_woC[idx] = __float2bfloat16(w_o[o * STATES + j4 * 4 + jj]);
        return;
    }
    idx -= 131072;
    if (idx < 131072) {                                        // woD
        int o2 = idx >> 10, rem = idx & 1023;
        int jp = rem >> 2, c = rem & 3;
        int j = jp * 2 + (c & 1), o = o2 * 2 + (c >> 1);
        g_woD[idx] = __float2bfloat16(w_o[o * STATES + j]);
        return;
    }
    idx -= 131072;
    {                                                          // wcE (32768)
        int j2 = idx >> 7, rem = idx & 127;
        int m = rem >> 1, jj = rem & 1;
        g_wcE[idx] = __float2bfloat16(w_c[(j2 * 2 + jj) * CAUSES + m]);
    }
}

// ---- dynamic smem layout (u64 units) ----
#define OFF_TH    0                   // [512][4] tanh(h_post) dup'd          2048
#define OFF_TP    2048                // [512][2] tanh(h_prior) row-pairs     1024
#define OFF_ERR   3072                // [256][4] error dup'd                 1024
#define OFF_EH    4096                // [256][4] error_h j-pairs             1024
#define OFF_C     5120                // [64][4]  c dup'd                      256
#define OFF_HP    5376                // [256][4] h_prior packed (hp0,hp1)    1024
#define OFF_PART  6400                // [3][256][4] partials                 3072
#define SMEM_U64  9472
#define SMEM_BYTES (SMEM_U64 * 8)

// ---------------- main persistent recurrence kernel (4-way split, bf16 weights) ----
__global__ __launch_bounds__(NT, 1)
void pc_rnn_kernel(const float* __restrict__ x,
                   const float* __restrict__ c_init,
                   const float* __restrict__ h_init,
                   const float* __restrict__ b_o,
                   const float* __restrict__ b_r,
                   float* __restrict__ out)
{
    extern __shared__ __align__(16) u64 S[];
    u64* s_th2  = S + OFF_TH;
    u64* s_tp2  = S + OFF_TP;
    u64* s_err2 = S + OFF_ERR;
    u64* s_eh2  = S + OFF_EH;
    u64* s_c2   = S + OFF_C;
    u64* s_hp   = S + OFF_HP;
    u64* s_part = S + OFF_PART;

    const int tid = threadIdx.x;
    const int lid = tid & (QT - 1);
    const int q   = tid >> 8;                 // quarter 0 = finalizer
    const int b0  = blockIdx.x * RPC;
    const int j0  = lid * 2;

    const uint2* __restrict__ wrB = (const uint2*)g_wrP;   // 4 bf16 per load
    const uint2* __restrict__ wcB = (const uint2*)g_wcB;
    const uint2* __restrict__ woC = (const uint2*)g_woC;
    const uint2* __restrict__ woD = (const uint2*)g_woD;
    const u32*   __restrict__ wcE = (const u32*)g_wcE;     // 2 bf16 per load

    float h0[RPC], h1[RPC];
    float rb0 = 0.f, rb1 = 0.f, rbo = 0.f, creg = 0.f;
    const int cm = lid & 63, cr = lid >> 6;

    if (q == 0) {
#pragma unroll
        for (int r = 0; r < RPC; ++r) {
            h0[r] = h_init[(size_t)(b0 + r) * STATES + j0];
            h1[r] = h_init[(size_t)(b0 + r) * STATES + j0 + 1];
            s_th2[(j0)     * RPC + r] = dup2(tanhf(h0[r]));
            s_th2[(j0 + 1) * RPC + r] = dup2(tanhf(h1[r]));
        }
        rb0 = b_r[j0]; rb1 = b_r[j0 + 1];
        rbo = b_o[lid];
        creg = c_init[(size_t)(b0 + cr) * CAUSES + cm];
        s_c2[cm * RPC + cr] = dup2(creg);
    }
    __syncthreads();

    for (int t = 0; t < SEQ_LEN; ++t) {
        // prefetch x_t (finalizer quarter; hidden behind phase B)
        float xr[RPC];
        if (q == 0) {
#pragma unroll
            for (int r = 0; r < RPC; ++r)
                xr[r] = x[((size_t)t * BATCH + b0 + r) * OUT_DIM + lid];
        }

        // ---------- Phase B partial: th@WrT + c@WcT over this quarter's k range ----------
        u64 acc[RPC];
#pragma unroll
        for (int r = 0; r < RPC; ++r) acc[r] = 0ULL;
        {
            const int bk2 = q * 64;
#pragma unroll 8
            for (int k2i = 0; k2i < 64; ++k2i) {
                const int k2 = bk2 + k2i;
                uint2 wv = wrB[k2 * 256 + lid];
                const int k = k2 * 2;
                ulonglong2 ta = *(const ulonglong2*)&s_th2[k * RPC];
                ulonglong2 tb = *(const ulonglong2*)&s_th2[k * RPC + 2];
                ulonglong2 tc = *(const ulonglong2*)&s_th2[k * RPC + 4];
                ulonglong2 td = *(const ulonglong2*)&s_th2[k * RPC + 6];
                u64 wlo = bf2(wv.x), whi = bf2(wv.y);
                fma2(acc[0], ta.x, wlo);
                fma2(acc[1], ta.y, wlo);
                fma2(acc[2], tb.x, wlo);
                fma2(acc[3], tb.y, wlo);
                fma2(acc[0], tc.x, whi);
                fma2(acc[1], tc.y, whi);
                fma2(acc[2], td.x, whi);
                fma2(acc[3], td.y, whi);
            }
            const int bm2 = q * 8;
#pragma unroll 8
            for (int m2i = 0; m2i < 8; ++m2i) {
                const int m2 = bm2 + m2i;
                uint2 wv = wcB[m2 * 256 + lid];
                const int m = m2 * 2;
                ulonglong2 ca_ = *(const ulonglong2*)&s_c2[m * RPC];
                ulonglong2 cb_ = *(const ulonglong2*)&s_c2[m * RPC + 2];
                ulonglong2 cc_ = *(const ulonglong2*)&s_c2[m * RPC + 4];
                ulonglong2 cd_ = *(const ulonglong2*)&s_c2[m * RPC + 6];
                u64 wlo = bf2(wv.x), whi = bf2(wv.y);
                fma2(acc[0], ca_.x, wlo);
                fma2(acc[1], ca_.y, wlo);
                fma2(acc[2], cb_.x, wlo);
                fma2(acc[3], cb_.y, wlo);
                fma2(acc[0], cc_.x, whi);
                fma2(acc[1], cc_.y, whi);
                fma2(acc[2], cd_.x, whi);
                fma2(acc[3], cd_.y, whi);
            }
        }
        if (q) {
#pragma unroll
            for (int r = 0; r < RPC; ++r) s_part[(q - 1) * 1024 + lid * 4 + r] = acc[r];
        }
        __syncthreads();

        // ---------- Phase B finalize: h_prior, tanh(h_prior) ----------
        if (q == 0) {
#pragma unroll
            for (int r = 0; r < RPC; ++r) {
                add2(acc[r], acc[r], s_part[lid * 4 + r]);
                add2(acc[r], acc[r], s_part[1024 + lid * 4 + r]);
                add2(acc[r], acc[r], s_part[2048 + lid * 4 + r]);
            }
            float tp0[RPC], tp1[RPC];
#pragma unroll
            for (int r = 0; r < RPC; ++r) {
                float a0, a1; unpack2(acc[r], a0, a1);
                float p0 = 0.9f * h0[r] + 0.1f * (a0 + rb0);
                float p1 = 0.9f * h1[r] + 0.1f * (a1 + rb1);
                s_hp[lid * 4 + r] = pack2(p0, p1);
                tp0[r] = tanhf(p0);
                tp1[r] = tanhf(p1);
            }
            ulonglong2 v0, v1;
            v0.x = pack2(tp0[0], tp0[1]); v0.y = pack2(tp0[2], tp0[3]);
            v1.x = pack2(tp1[0], tp1[1]); v1.y = pack2(tp1[2], tp1[3]);
            *(ulonglong2*)&s_tp2[j0 * 2]     = v0;
            *(ulonglong2*)&s_tp2[j0 * 2 + 2] = v1;
        }
        __syncthreads();

        // ---------- Phase C partial: tp@WoT over this quarter's j range (o = lid) ----------
        {
            u64 e01 = 0ULL, e23 = 0ULL;
            const int bj4 = q * 32;
#pragma unroll 8
            for (int j4i = 0; j4i < 32; ++j4i) {
                const int j4 = bj4 + j4i;
                uint2 wv = woC[j4 * 256 + lid];
                ulonglong2 p0 = *(const ulonglong2*)&s_tp2[(j4 * 4 + 0) * 2];
                ulonglong2 p1 = *(const ulonglong2*)&s_tp2[(j4 * 4 + 1) * 2];
                ulonglong2 p2 = *(const ulonglong2*)&s_tp2[(j4 * 4 + 2) * 2];
                ulonglong2 p3 = *(const ulonglong2*)&s_tp2[(j4 * 4 + 3) * 2];
                u64 w0, w1, w2, w3;
                bfdup(wv.x, w0, w1);
                bfdup(wv.y, w2, w3);
                fma2(e01, p0.x, w0); fma2(e23, p0.y, w0);
                fma2(e01, p1.x, w1); fma2(e23, p1.y, w1);
                fma2(e01, p2.x, w2); fma2(e23, p2.y, w2);
                fma2(e01, p3.x, w3); fma2(e23, p3.y, w3);
            }
            if (q) {
                s_part[(q - 1) * 1024 + lid * 4]     = e01;
                s_part[(q - 1) * 1024 + lid * 4 + 1] = e23;
            } else {
                acc[0] = e01; acc[1] = e23;
            }
        }
        __syncthreads();

        // ---------- Phase C finalize: err = pred - x_t; out + s_err2 ----------
        if (q == 0) {
            add2(acc[0], acc[0], s_part[lid * 4]);
            add2(acc[0], acc[0], s_part[1024 + lid * 4]);
            add2(acc[0], acc[0], s_part[2048 + lid * 4]);
            add2(acc[1], acc[1], s_part[lid * 4 + 1]);
            add2(acc[1], acc[1], s_part[1024 + lid * 4 + 1]);
            add2(acc[1], acc[1], s_part[2048 + lid * 4 + 1]);
            float q0, q1, q2, q3;
            unpack2(acc[0], q0, q1); unpack2(acc[1], q2, q3);
            float er0 = (q0 + rbo) - xr[0];
            float er1 = (q1 + rbo) - xr[1];
            float er2 = (q2 + rbo) - xr[2];
            float er3 = (q3 + rbo) - xr[3];
            size_t ob = ((size_t)t * BATCH + b0) * OUT_DIM + lid;
            out[ob]               = er0;
            out[ob + OUT_DIM]     = er1;
            out[ob + 2 * OUT_DIM] = er2;
            out[ob + 3 * OUT_DIM] = er3;
            ulonglong2 s0, s1;
            s0.x = dup2(er0); s0.y = dup2(er1);
            s1.x = dup2(er2); s1.y = dup2(er3);
            *(ulonglong2*)&s_err2[lid * RPC]     = s0;
            *(ulonglong2*)&s_err2[lid * RPC + 2] = s1;
        }
        __syncthreads();

        // ---------- Phase D partial: err@Wo over this quarter's o range ----------
        {
            u64 g[RPC];
#pragma unroll
            for (int r = 0; r < RPC; ++r) g[r] = 0ULL;
            const int bo2 = q * 32;
#pragma unroll 8
            for (int o2i = 0; o2i < 32; ++o2i) {
                const int o2 = bo2 + o2i;
                uint2 wv = woD[o2 * 256 + lid];
                const int o = o2 * 2;
                ulonglong2 ea = *(const ulonglong2*)&s_err2[o * RPC];
                ulonglong2 eb = *(const ulonglong2*)&s_err2[o * RPC + 2];
                ulonglong2 ec = *(const ulonglong2*)&s_err2[o * RPC + 4];
                ulonglong2 ed = *(const ulonglong2*)&s_err2[o * RPC + 6];
                u64 wlo = bf2(wv.x), whi = bf2(wv.y);
                fma2(g[0], ea.x, wlo);
                fma2(g[1], ea.y, wlo);
                fma2(g[2], eb.x, wlo);
                fma2(g[3], eb.y, wlo);
                fma2(g[0], ec.x, whi);
                fma2(g[1], ec.y, whi);
                fma2(g[2], ed.x, whi);
                fma2(g[3], ed.y, whi);
            }
            if (q) {
#pragma unroll
                for (int r = 0; r < RPC; ++r) s_part[(q - 1) * 1024 + lid * 4 + r] = g[r];
            } else {
#pragma unroll
                for (int r = 0; r < RPC; ++r) acc[r] = g[r];
            }
        }
        __syncthreads();

        // ---------- Phase D finalize: h_post, th = tanh(h_post), eh ----------
        if (q == 0) {
            u64 ep[RPC];
#pragma unroll
            for (int r = 0; r < RPC; ++r) {
                add2(acc[r], acc[r], s_part[lid * 4 + r]);
                add2(acc[r], acc[r], s_part[1024 + lid * 4 + r]);
                add2(acc[r], acc[r], s_part[2048 + lid * 4 + r]);
                float g0, g1; unpack2(acc[r], g0, g1);
                float t0a, t1a;
                {
                    u64 tpa = s_tp2[j0 * 2 + (r >> 1)];
                    u64 tpb = s_tp2[(j0 + 1) * 2 + (r >> 1)];
                    float x0, x1, y0, y1;
                    unpack2(tpa, x0, x1); unpack2(tpb, y0, y1);
                    t0a = (r & 1) ? x1 : x0;
                    t1a = (r & 1) ? y1 : y0;
                }
                float p0, p1; unpack2(s_hp[lid * 4 + r], p0, p1);
                float d0 = ALPHA_X * (1.0f - t0a * t0a) * g0;
                float d1 = ALPHA_X * (1.0f - t1a * t1a) * g1;
                h0[r] = p0 - d0;
                h1[r] = p1 - d1;
                ep[r] = pack2(d0, d1);
                s_th2[(j0)     * RPC + r] = dup2(tanhf(h0[r]));
                s_th2[(j0 + 1) * RPC + r] = dup2(tanhf(h1[r]));
            }
            ulonglong2 ev0, ev1;
            ev0.x = ep[0]; ev0.y = ep[1]; ev1.x = ep[2]; ev1.y = ep[3];
            *(ulonglong2*)&s_eh2[lid * RPC]     = ev0;
            *(ulonglong2*)&s_eh2[lid * RPC + 2] = ev1;
        }
        __syncthreads();

        // ---------- Phase E partial: eh@Wc over this quarter's j range ----------
        {
            u64 ce0 = 0ULL, ce1 = 0ULL;
            const int bj2 = q * 64;
#pragma unroll 8
            for (int j2i = 0; j2i < 64; j2i += 2) {
                const int j2 = bj2 + j2i;
                fma2(ce0, s_eh2[j2 * RPC + cr],       bf2(wcE[j2 * 64 + cm]));
                fma2(ce1, s_eh2[(j2 + 1) * RPC + cr], bf2(wcE[(j2 + 1) * 64 + cm]));
            }
            u64 ca;
            add2(ca, ce0, ce1);
            if (q) s_part[(q - 1) * 1024 + lid] = ca;
            else   acc[0] = ca;
        }
        __syncthreads();

        // ---------- Phase E finalize: c update ----------
        if (q == 0) {
            add2(acc[0], acc[0], s_part[lid]);
            add2(acc[0], acc[0], s_part[1024 + lid]);
            add2(acc[0], acc[0], s_part[2048 + lid]);
            float cl, ch;
            unpack2(acc[0], cl, ch);
            creg = creg - ALPHA_H * (cl + ch);
            s_c2[cm * RPC + cr] = dup2(creg);
        }
        __syncthreads();
    }
}

extern "C" void kernel_launch(void* const* d_in, const int* in_sizes, int n_in,
                              void* d_out, int out_size) {
    const float* x      = (const float*)d_in[0];
    const float* c_init = (const float*)d_in[1];
    const float* h_init = (const float*)d_in[2];
    const float* w_o    = (const float*)d_in[3];
    const float* b_o    = (const float*)d_in[4];
    const float* w_c    = (const float*)d_in[5];
    const float* w_r    = (const float*)d_in[6];
    const float* b_r    = (const float*)d_in[7];
    float* out          = (float*)d_out;

    pack_all<<<2304, 256>>>(w_r, w_c, w_o);

    cudaFuncSetAttribute(pc_rnn_kernel,
                         cudaFuncAttributeMaxDynamicSharedMemorySize, SMEM_BYTES);
    pc_rnn_kernel<<<NCTA, NT, SMEM_BYTES>>>(x, c_init, h_init, b_o, b_r, out);
}